// round 6
// baseline (speedup 1.0000x reference)
#include <cuda_runtime.h>
#include <cuda_bf16.h>
#include <cstdint>
#include <cstddef>

// ---------------------------------------------------------------------------
// Problem constants
// ---------------------------------------------------------------------------
#define HDIM 1024
#define IDIM 2048
#define NEXP 8
#define NTOK 4096
#define SEG  4096
#define NSEG 9               // 8 routed experts + 1 shared "expert"
#define STAGES 4

#define OUT_AUX    ((size_t)NTOK * HDIM)
#define OUT_Z      (OUT_AUX + 1)
#define OUT_LOGITS (OUT_AUX + 2)

// ---------------------------------------------------------------------------
// Static device scratch
// ---------------------------------------------------------------------------
__device__ int   g_row_token[NEXP * SEG];
__device__ float g_row_weight[NEXP * SEG];
__device__ int   g_cnt[NEXP];
__device__ int   g_disp[NEXP];
__device__ float g_psum[NEXP];
__device__ float g_zsum;

// bf16 hi/lo split copies of all GEMM operands (converted once per launch)
__device__ __nv_bfloat16 g_xh[(size_t)NTOK * HDIM];
__device__ __nv_bfloat16 g_xl[(size_t)NTOK * HDIM];
__device__ __nv_bfloat16 g_gwh[(size_t)NEXP * HDIM * IDIM];
__device__ __nv_bfloat16 g_gwl[(size_t)NEXP * HDIM * IDIM];
__device__ __nv_bfloat16 g_uwh[(size_t)NEXP * HDIM * IDIM];
__device__ __nv_bfloat16 g_uwl[(size_t)NEXP * HDIM * IDIM];
__device__ __nv_bfloat16 g_dwh[(size_t)NEXP * IDIM * HDIM];
__device__ __nv_bfloat16 g_dwl[(size_t)NEXP * IDIM * HDIM];
__device__ __nv_bfloat16 g_sgwh[(size_t)HDIM * IDIM];
__device__ __nv_bfloat16 g_sgwl[(size_t)HDIM * IDIM];
__device__ __nv_bfloat16 g_suwh[(size_t)HDIM * IDIM];
__device__ __nv_bfloat16 g_suwl[(size_t)HDIM * IDIM];
__device__ __nv_bfloat16 g_sdwh[(size_t)IDIM * HDIM];
__device__ __nv_bfloat16 g_sdwl[(size_t)IDIM * HDIM];
__device__ __nv_bfloat16 g_o1h[(size_t)NSEG * SEG * IDIM];
__device__ __nv_bfloat16 g_o1l[(size_t)NSEG * SEG * IDIM];

// ---------------------------------------------------------------------------
// Helpers
// ---------------------------------------------------------------------------
__device__ __forceinline__ uint32_t smaddr(const void* p) {
    return (uint32_t)__cvta_generic_to_shared(p);
}
__device__ __forceinline__ void ldsm4(uint32_t r[4], uint32_t a) {
    asm volatile("ldmatrix.sync.aligned.m8n8.x4.shared.b16 {%0,%1,%2,%3},[%4];"
        : "=r"(r[0]), "=r"(r[1]), "=r"(r[2]), "=r"(r[3]) : "r"(a));
}
__device__ __forceinline__ void ldsm4t(uint32_t r[4], uint32_t a) {
    asm volatile("ldmatrix.sync.aligned.m8n8.x4.trans.shared.b16 {%0,%1,%2,%3},[%4];"
        : "=r"(r[0]), "=r"(r[1]), "=r"(r[2]), "=r"(r[3]) : "r"(a));
}
__device__ __forceinline__ void mma_bf16(float c[4], const uint32_t a[4],
                                         const uint32_t b[2]) {
    asm volatile(
        "mma.sync.aligned.m16n8k16.row.col.f32.bf16.bf16.f32 "
        "{%0,%1,%2,%3},{%4,%5,%6,%7},{%8,%9},{%0,%1,%2,%3};"
        : "+f"(c[0]), "+f"(c[1]), "+f"(c[2]), "+f"(c[3])
        : "r"(a[0]), "r"(a[1]), "r"(a[2]), "r"(a[3]), "r"(b[0]), "r"(b[1]));
}
__device__ __forceinline__ void split2(float x, float y, uint32_t& hi, uint32_t& lo) {
    __nv_bfloat16 hx = __float2bfloat16(x), hy = __float2bfloat16(y);
    __nv_bfloat16 lx = __float2bfloat16(x - __bfloat162float(hx));
    __nv_bfloat16 ly = __float2bfloat16(y - __bfloat162float(hy));
    hi = (uint32_t)__bfloat16_as_ushort(hx) | ((uint32_t)__bfloat16_as_ushort(hy) << 16);
    lo = (uint32_t)__bfloat16_as_ushort(lx) | ((uint32_t)__bfloat16_as_ushort(ly) << 16);
}
__device__ __forceinline__ void cp16(void* dst, const void* src) {
    asm volatile("cp.async.cg.shared.global [%0],[%1],16;"
        :: "r"(smaddr(dst)), "l"(src));
}
__device__ __forceinline__ void cp_commit() {
    asm volatile("cp.async.commit_group;");
}
template <int N> __device__ __forceinline__ void cp_wait() {
    asm volatile("cp.async.wait_group %0;" :: "n"(N));
}

// ---------------------------------------------------------------------------
// Init
// ---------------------------------------------------------------------------
__global__ void init_kernel() {
    int tid = blockIdx.x * blockDim.x + threadIdx.x;
    int stride = gridDim.x * blockDim.x;
    for (int i = tid; i < NEXP * SEG; i += stride) {
        g_row_token[i] = 0;
        g_row_weight[i] = 0.0f;
    }
    if (tid < NEXP) { g_cnt[tid] = 0; g_disp[tid] = 0; g_psum[tid] = 0.0f; }
    if (tid == 0) g_zsum = 0.0f;
}

// ---------------------------------------------------------------------------
// fp32 -> bf16 hi/lo split conversion for all operands. blockIdx.y = tensor.
// ---------------------------------------------------------------------------
__global__ __launch_bounds__(256) void convert_kernel(
    const float* __restrict__ x, const float* __restrict__ gw,
    const float* __restrict__ uw, const float* __restrict__ dw,
    const float* __restrict__ sgw, const float* __restrict__ suw,
    const float* __restrict__ sdw)
{
    const float* src; __nv_bfloat16 *dh, *dl; size_t n;
    switch (blockIdx.y) {
        case 0: src = x;   dh = g_xh;   dl = g_xl;   n = (size_t)NTOK * HDIM; break;
        case 1: src = gw;  dh = g_gwh;  dl = g_gwl;  n = (size_t)NEXP * HDIM * IDIM; break;
        case 2: src = uw;  dh = g_uwh;  dl = g_uwl;  n = (size_t)NEXP * HDIM * IDIM; break;
        case 3: src = dw;  dh = g_dwh;  dl = g_dwl;  n = (size_t)NEXP * IDIM * HDIM; break;
        case 4: src = sgw; dh = g_sgwh; dl = g_sgwl; n = (size_t)HDIM * IDIM; break;
        case 5: src = suw; dh = g_suwh; dl = g_suwl; n = (size_t)HDIM * IDIM; break;
        default: src = sdw; dh = g_sdwh; dl = g_sdwl; n = (size_t)IDIM * HDIM; break;
    }
    size_t n4 = n >> 2;
    size_t stride = (size_t)gridDim.x * blockDim.x;
    for (size_t i = (size_t)blockIdx.x * blockDim.x + threadIdx.x; i < n4; i += stride) {
        float4 v = ((const float4*)src)[i];
        uint32_t h0, l0, h1, l1;
        split2(v.x, v.y, h0, l0);
        split2(v.z, v.w, h1, l1);
        ((uint2*)dh)[i] = make_uint2(h0, h1);
        ((uint2*)dl)[i] = make_uint2(l0, l1);
    }
}

// ---------------------------------------------------------------------------
// Router (unchanged — validated at 1e-6)
// ---------------------------------------------------------------------------
__global__ __launch_bounds__(256) void router_kernel(
    const float* __restrict__ x, const float* __restrict__ rw,
    float* __restrict__ out)
{
    __shared__ float s_rw[HDIM * NEXP];
    int tid = threadIdx.x;
    for (int i = tid; i < HDIM * NEXP; i += 256) s_rw[i] = rw[i];
    __syncthreads();

    int warp = tid >> 5, lane = tid & 31;
    int t = blockIdx.x * 8 + warp;

    float acc[NEXP];
#pragma unroll
    for (int e = 0; e < NEXP; e++) acc[e] = 0.0f;

    const float* xr = x + (size_t)t * HDIM;
    for (int h0 = 0; h0 < HDIM; h0 += 32) {
        float xv = xr[h0 + lane];
        const float4* r = (const float4*)&s_rw[(size_t)(h0 + lane) * NEXP];
        float4 r0 = r[0], r1 = r[1];
        acc[0] += xv * r0.x; acc[1] += xv * r0.y;
        acc[2] += xv * r0.z; acc[3] += xv * r0.w;
        acc[4] += xv * r1.x; acc[5] += xv * r1.y;
        acc[6] += xv * r1.z; acc[7] += xv * r1.w;
    }
#pragma unroll
    for (int e = 0; e < NEXP; e++)
#pragma unroll
        for (int off = 16; off; off >>= 1)
            acc[e] += __shfl_xor_sync(0xffffffffu, acc[e], off);

    if (lane == 0) {
        float mx = acc[0];
#pragma unroll
        for (int e = 1; e < NEXP; e++) mx = fmaxf(mx, acc[e]);
        float p[NEXP], s = 0.0f;
#pragma unroll
        for (int e = 0; e < NEXP; e++) { p[e] = expf(acc[e] - mx); s += p[e]; }
        float inv = 1.0f / s;
#pragma unroll
        for (int e = 0; e < NEXP; e++) p[e] *= inv;

        float lse = logf(s) + mx;
        atomicAdd(&g_zsum, lse * lse);
#pragma unroll
        for (int e = 0; e < NEXP; e++) atomicAdd(&g_psum[e], p[e]);
#pragma unroll
        for (int e = 0; e < NEXP; e++)
            out[OUT_LOGITS + (size_t)t * NEXP + e] = acc[e];

        int e1 = 0;
#pragma unroll
        for (int e = 1; e < NEXP; e++) if (p[e] > p[e1]) e1 = e;
        int e2 = (e1 == 0) ? 1 : 0;
#pragma unroll
        for (int e = 0; e < NEXP; e++) if (e != e1 && p[e] > p[e2]) e2 = e;

        float ws = p[e1] + p[e2];
        float w1 = p[e1] / ws, w2 = p[e2] / ws;
        atomicAdd(&g_disp[e1], 1);
        atomicAdd(&g_disp[e2], 1);
        int p1 = atomicAdd(&g_cnt[e1], 1);
        g_row_token[e1 * SEG + p1] = t;
        g_row_weight[e1 * SEG + p1] = w1;
        int p2 = atomicAdd(&g_cnt[e2], 1);
        g_row_token[e2 * SEG + p2] = t;
        g_row_weight[e2 * SEG + p2] = w2;
    }
}

__global__ void finalize_kernel(float* __restrict__ out) {
    if (threadIdx.x == 0 && blockIdx.x == 0) {
        float aux = 0.0f;
        for (int e = 0; e < NEXP; e++) {
            float tpe = (float)g_disp[e] / (2.0f * (float)NTOK);
            float ppe = g_psum[e] / (float)NTOK;
            aux += tpe * ppe;
        }
        out[OUT_AUX] = (float)NEXP * aux;
        out[OUT_Z] = g_zsum / (float)NTOK;
    }
}

// ---------------------------------------------------------------------------
// Shared-memory stage structs (dynamic smem, 4 stages)
// BM=128, BN=256. A: 128x16 per stage. B: 16x256 per stage (hi/lo each).
// ---------------------------------------------------------------------------
struct alignas(16) G1Smem {
    __nv_bfloat16 Ah[STAGES][128][24];
    __nv_bfloat16 Al[STAGES][128][24];
    __nv_bfloat16 Bh[STAGES][16][264];   // cols 0-127 gate, 128-255 up
    __nv_bfloat16 Bl[STAGES][16][264];
    int tok[128];
};
struct alignas(16) G2Smem {
    __nv_bfloat16 Ah[STAGES][128][24];
    __nv_bfloat16 Al[STAGES][128][24];
    __nv_bfloat16 Bh[STAGES][16][264];
    __nv_bfloat16 Bl[STAGES][16][264];
    int   tok[128];
    float w[128];
};

// ---------------------------------------------------------------------------
// GEMM1: gathered rows -> silu(X@Gw) * (X@Uw), bf16x3, cp.async 4-stage.
// Block 128 x (128 gate + 128 up), 512 threads / 16 warps.
// Warp tile: 32 rows x (32 gate + 32 up) cols. wm = wid&3, wn = wid>>2.
// ---------------------------------------------------------------------------
__global__ __launch_bounds__(512, 1) void gemm1_kernel()
{
    const int seg = blockIdx.y >> 5;
    const int base_m = (blockIdx.y & 31) * 128;
    const __nv_bfloat16 *gwh, *gwl, *uwh, *uwl;
    if (seg < NEXP) {
        if (base_m >= g_cnt[seg]) return;
        size_t off = (size_t)seg * HDIM * IDIM;
        gwh = g_gwh + off; gwl = g_gwl + off;
        uwh = g_uwh + off; uwl = g_uwl + off;
    } else {
        gwh = g_sgwh; gwl = g_sgwl; uwh = g_suwh; uwl = g_suwl;
    }

    extern __shared__ char smem_raw[];
    G1Smem& S = *(G1Smem*)smem_raw;

    const int tid = threadIdx.x;
    const int lane = tid & 31, wid = tid >> 5;
    const int wm = wid & 3, wn = wid >> 2;
    const int nb = blockIdx.x;

    if (tid < 128)
        S.tok[tid] = (seg < NEXP) ? g_row_token[seg * SEG + base_m + tid]
                                  : (base_m + tid);
    __syncthreads();

    // A: 256 16B-chunks per buffer; tid<256 -> Ah, tid>=256 -> Al
    const int atid = tid & 255;
    const int am = atid >> 1, ac = (atid & 1) * 8;
    const bool aLo = tid >= 256;
    const __nv_bfloat16* aSrc =
        (aLo ? g_xl : g_xh) + (size_t)S.tok[am] * HDIM + ac;
    // B: 512 chunks per buffer; every thread does 1 Bh + 1 Bl chunk
    const int brow = tid >> 5, bcol = (tid & 31) * 8;
    const __nv_bfloat16 *bSrcH, *bSrcL;
    {
        size_t boff = (size_t)brow * IDIM + nb * 128;
        if (bcol < 128) { bSrcH = gwh + boff + bcol;       bSrcL = gwl + boff + bcol; }
        else            { bSrcH = uwh + boff + bcol - 128; bSrcL = uwl + boff + bcol - 128; }
    }

    float acc[2][8][4];
#pragma unroll
    for (int i = 0; i < 2; i++)
#pragma unroll
        for (int j = 0; j < 8; j++)
#pragma unroll
            for (int q = 0; q < 4; q++) acc[i][j][q] = 0.0f;

    const int KSTEPS = HDIM / 16;   // 64
#pragma unroll 1
    for (int s = 0; s < STAGES - 1; s++) {
        int k0 = s * 16;
        cp16(aLo ? &S.Al[s][am][ac] : &S.Ah[s][am][ac], aSrc + k0);
        cp16(&S.Bh[s][brow][bcol], bSrcH + (size_t)k0 * IDIM);
        cp16(&S.Bl[s][brow][bcol], bSrcL + (size_t)k0 * IDIM);
        cp_commit();
    }

#pragma unroll 1
    for (int kt = 0; kt < KSTEPS; kt++) {
        cp_wait<STAGES - 2>();
        __syncthreads();

        int kn = kt + STAGES - 1;
        if (kn < KSTEPS) {
            int sn = kn & (STAGES - 1);
            int k0 = kn * 16;
            cp16(aLo ? &S.Al[sn][am][ac] : &S.Ah[sn][am][ac], aSrc + k0);
            cp16(&S.Bh[sn][brow][bcol], bSrcH + (size_t)k0 * IDIM);
            cp16(&S.Bl[sn][brow][bcol], bSrcL + (size_t)k0 * IDIM);
        }
        cp_commit();

        const int s = kt & (STAGES - 1);
        uint32_t ah[2][4], al[2][4];
#pragma unroll
        for (int mt = 0; mt < 2; mt++) {
            int r = wm * 32 + mt * 16 + (lane & 15);
            int c = (lane >> 4) * 8;
            ldsm4(ah[mt], smaddr(&S.Ah[s][r][c]));
            ldsm4(al[mt], smaddr(&S.Al[s][r][c]));
        }
#pragma unroll
        for (int g = 0; g < 4; g++) {
            int n0 = (g < 2) ? (wn * 32 + g * 16)
                             : (128 + wn * 32 + (g - 2) * 16);
            int bc = n0 + (lane >> 4) * 8;
            int brr = lane & 15;
            uint32_t bh[4], bl[4];
            ldsm4t(bh, smaddr(&S.Bh[s][brr][bc]));
            ldsm4t(bl, smaddr(&S.Bl[s][brr][bc]));
            int j = g * 2;
#pragma unroll
            for (int mt = 0; mt < 2; mt++) {
                mma_bf16(acc[mt][j],     ah[mt], bh);
                mma_bf16(acc[mt][j],     ah[mt], bl);
                mma_bf16(acc[mt][j],     al[mt], bh);
                mma_bf16(acc[mt][j + 1], ah[mt], bh + 2);
                mma_bf16(acc[mt][j + 1], ah[mt], bl + 2);
                mma_bf16(acc[mt][j + 1], al[mt], bh + 2);
            }
        }
    }

    // epilogue: silu(gate)*up -> g_o1h/g_o1l  (j 0-3 gate, 4-7 up, same cols)
#pragma unroll
    for (int mt = 0; mt < 2; mt++) {
        int r0 = base_m + wm * 32 + mt * 16 + (lane >> 2);
        size_t row0 = (size_t)seg * SEG + r0;
        size_t row1 = row0 + 8;
#pragma unroll
        for (int jg = 0; jg < 4; jg++) {
            float* G = acc[mt][jg];
            float* U = acc[mt][4 + jg];
            int col = nb * 128 + wn * 32 + jg * 8 + (lane & 3) * 2;
            float o0 = U[0] * G[0] / (1.0f + expf(-G[0]));
            float o1 = U[1] * G[1] / (1.0f + expf(-G[1]));
            float o2 = U[2] * G[2] / (1.0f + expf(-G[2]));
            float o3 = U[3] * G[3] / (1.0f + expf(-G[3]));
            uint32_t h01, l01, h23, l23;
            split2(o0, o1, h01, l01);
            split2(o2, o3, h23, l23);
            *(uint32_t*)&g_o1h[row0 * IDIM + col] = h01;
            *(uint32_t*)&g_o1l[row0 * IDIM + col] = l01;
            *(uint32_t*)&g_o1h[row1 * IDIM + col] = h23;
            *(uint32_t*)&g_o1l[row1 * IDIM + col] = l23;
        }
    }
}

// ---------------------------------------------------------------------------
// GEMM2: g_o1 @ down_w, weight-scaled atomic scatter.
// Block 128 x 256, 512 threads / 16 warps, warp tile 32x64.
// ---------------------------------------------------------------------------
__global__ __launch_bounds__(512, 1) void gemm2_kernel(float* __restrict__ out)
{
    const int seg = blockIdx.y >> 5;
    const int base_m = (blockIdx.y & 31) * 128;
    const __nv_bfloat16 *bwh, *bwl;
    if (seg < NEXP) {
        if (base_m >= g_cnt[seg]) return;
        size_t off = (size_t)seg * IDIM * HDIM;
        bwh = g_dwh + off; bwl = g_dwl + off;
    } else { bwh = g_sdwh; bwl = g_sdwl; }

    extern __shared__ char smem_raw[];
    G2Smem& S = *(G2Smem*)smem_raw;

    const int tid = threadIdx.x;
    const int lane = tid & 31, wid = tid >> 5;
    const int wm = wid & 3, wn = wid >> 2;
    const int nb = blockIdx.x;

    if (tid < 128) {
        if (seg < NEXP) {
            S.tok[tid] = g_row_token[seg * SEG + base_m + tid];
            S.w[tid]   = g_row_weight[seg * SEG + base_m + tid];
        } else { S.tok[tid] = base_m + tid; S.w[tid] = 1.0f; }
    }
    __syncthreads();

    const int atid = tid & 255;
    const int am = atid >> 1, ac = (atid & 1) * 8;
    const bool aLo = tid >= 256;
    const size_t arow = ((size_t)seg * SEG + base_m + am) * IDIM + ac;
    const __nv_bfloat16* aSrc = (aLo ? g_o1l : g_o1h) + arow;
    const int brow = tid >> 5, bcol = (tid & 31) * 8;
    const size_t boff = (size_t)brow * HDIM + nb * 256 + bcol;
    const __nv_bfloat16* bSrcH = bwh + boff;
    const __nv_bfloat16* bSrcL = bwl + boff;

    float acc[2][8][4];
#pragma unroll
    for (int i = 0; i < 2; i++)
#pragma unroll
        for (int j = 0; j < 8; j++)
#pragma unroll
            for (int q = 0; q < 4; q++) acc[i][j][q] = 0.0f;

    const int KSTEPS = IDIM / 16;   // 128
#pragma unroll 1
    for (int s = 0; s < STAGES - 1; s++) {
        int k0 = s * 16;
        cp16(aLo ? &S.Al[s][am][ac] : &S.Ah[s][am][ac], aSrc + k0);
        cp16(&S.Bh[s][brow][bcol], bSrcH + (size_t)k0 * HDIM);
        cp16(&S.Bl[s][brow][bcol], bSrcL + (size_t)k0 * HDIM);
        cp_commit();
    }

#pragma unroll 1
    for (int kt = 0; kt < KSTEPS; kt++) {
        cp_wait<STAGES - 2>();
        __syncthreads();

        int kn = kt + STAGES - 1;
        if (kn < KSTEPS) {
            int sn = kn & (STAGES - 1);
            int k0 = kn * 16;
            cp16(aLo ? &S.Al[sn][am][ac] : &S.Ah[sn][am][ac], aSrc + k0);
            cp16(&S.Bh[sn][brow][bcol], bSrcH + (size_t)k0 * HDIM);
            cp16(&S.Bl[sn][brow][bcol], bSrcL + (size_t)k0 * HDIM);
        }
        cp_commit();

        const int s = kt & (STAGES - 1);
        uint32_t ah[2][4], al[2][4];
#pragma unroll
        for (int mt = 0; mt < 2; mt++) {
            int r = wm * 32 + mt * 16 + (lane & 15);
            int c = (lane >> 4) * 8;
            ldsm4(ah[mt], smaddr(&S.Ah[s][r][c]));
            ldsm4(al[mt], smaddr(&S.Al[s][r][c]));
        }
#pragma unroll
        for (int g = 0; g < 4; g++) {
            int n0 = wn * 64 + g * 16;
            int bc = n0 + (lane >> 4) * 8;
            int brr = lane & 15;
            uint32_t bh[4], bl[4];
            ldsm4t(bh, smaddr(&S.Bh[s][brr][bc]));
            ldsm4t(bl, smaddr(&S.Bl[s][brr][bc]));
            int j = g * 2;
#pragma unroll
            for (int mt = 0; mt < 2; mt++) {
                mma_bf16(acc[mt][j],     ah[mt], bh);
                mma_bf16(acc[mt][j],     ah[mt], bl);
                mma_bf16(acc[mt][j],     al[mt], bh);
                mma_bf16(acc[mt][j + 1], ah[mt], bh + 2);
                mma_bf16(acc[mt][j + 1], ah[mt], bl + 2);
                mma_bf16(acc[mt][j + 1], al[mt], bh + 2);
            }
        }
    }

    // epilogue: weight-scaled scatter-add
#pragma unroll
    for (int mt = 0; mt < 2; mt++) {
        int rl0 = wm * 32 + mt * 16 + (lane >> 2);
        int t0 = S.tok[rl0], t1 = S.tok[rl0 + 8];
        float w0 = S.w[rl0], w1 = S.w[rl0 + 8];
#pragma unroll
        for (int j = 0; j < 8; j++) {
            float* C = acc[mt][j];
            int col = nb * 256 + wn * 64 + j * 8 + (lane & 3) * 2;
            atomicAdd(&out[(size_t)t0 * HDIM + col],     w0 * C[0]);
            atomicAdd(&out[(size_t)t0 * HDIM + col + 1], w0 * C[1]);
            atomicAdd(&out[(size_t)t1 * HDIM + col],     w1 * C[2]);
            atomicAdd(&out[(size_t)t1 * HDIM + col + 1], w1 * C[3]);
        }
    }
}

// ---------------------------------------------------------------------------
// Launch
// ---------------------------------------------------------------------------
extern "C" void kernel_launch(void* const* d_in, const int* in_sizes, int n_in,
                              void* d_out, int out_size) {
    (void)in_sizes; (void)n_in; (void)out_size;
    const float* x   = (const float*)d_in[0];
    const float* rw  = (const float*)d_in[1];
    const float* gw  = (const float*)d_in[2];
    const float* uw  = (const float*)d_in[3];
    const float* dw  = (const float*)d_in[4];
    const float* sgw = (const float*)d_in[5];
    const float* suw = (const float*)d_in[6];
    const float* sdw = (const float*)d_in[7];
    float* out = (float*)d_out;

    cudaFuncSetAttribute(gemm1_kernel,
        cudaFuncAttributeMaxDynamicSharedMemorySize, (int)sizeof(G1Smem));
    cudaFuncSetAttribute(gemm2_kernel,
        cudaFuncAttributeMaxDynamicSharedMemorySize, (int)sizeof(G2Smem));

    cudaMemsetAsync(d_out, 0, (size_t)NTOK * HDIM * sizeof(float));
    init_kernel<<<64, 256>>>();
    convert_kernel<<<dim3(2048, 7), 256>>>(x, gw, uw, dw, sgw, suw, sdw);
    router_kernel<<<NTOK / 8, 256>>>(x, rw, out);
    finalize_kernel<<<1, 32>>>(out);

    dim3 g1(IDIM / 128, NSEG * 32);     // (16, 288)
    gemm1_kernel<<<g1, 512, sizeof(G1Smem)>>>();

    dim3 g2(HDIM / 256, NSEG * 32);     // (4, 288)
    gemm2_kernel<<<g2, 512, sizeof(G2Smem)>>>(out);
}

// round 10
// speedup vs baseline: 1.0912x; 1.0912x over previous
#include <cuda_runtime.h>
#include <cuda_bf16.h>
#include <cstdint>
#include <cstddef>

// ---------------------------------------------------------------------------
// Problem constants
// ---------------------------------------------------------------------------
#define HDIM 1024
#define IDIM 2048
#define NEXP 8
#define NTOK 4096
#define SEG  4096
#define NSEG 9               // 8 routed experts + 1 shared "expert"
#define STAGES 5

#define OUT_AUX    ((size_t)NTOK * HDIM)
#define OUT_Z      (OUT_AUX + 1)
#define OUT_LOGITS (OUT_AUX + 2)

// ---------------------------------------------------------------------------
// Static device scratch
// ---------------------------------------------------------------------------
__device__ int   g_row_token[NEXP * SEG];
__device__ float g_row_weight[NEXP * SEG];
__device__ int   g_cnt[NEXP];
__device__ int   g_disp[NEXP];
__device__ float g_psum[NEXP];
__device__ float g_zsum;

// bf16 hi/lo split copies of all GEMM operands (converted once per launch)
__device__ __nv_bfloat16 g_xh[(size_t)NTOK * HDIM];
__device__ __nv_bfloat16 g_xl[(size_t)NTOK * HDIM];
__device__ __nv_bfloat16 g_gwh[(size_t)NEXP * HDIM * IDIM];
__device__ __nv_bfloat16 g_gwl[(size_t)NEXP * HDIM * IDIM];
__device__ __nv_bfloat16 g_uwh[(size_t)NEXP * HDIM * IDIM];
__device__ __nv_bfloat16 g_uwl[(size_t)NEXP * HDIM * IDIM];
__device__ __nv_bfloat16 g_dwh[(size_t)NEXP * IDIM * HDIM];
__device__ __nv_bfloat16 g_dwl[(size_t)NEXP * IDIM * HDIM];
__device__ __nv_bfloat16 g_sgwh[(size_t)HDIM * IDIM];
__device__ __nv_bfloat16 g_sgwl[(size_t)HDIM * IDIM];
__device__ __nv_bfloat16 g_suwh[(size_t)HDIM * IDIM];
__device__ __nv_bfloat16 g_suwl[(size_t)HDIM * IDIM];
__device__ __nv_bfloat16 g_sdwh[(size_t)IDIM * HDIM];
__device__ __nv_bfloat16 g_sdwl[(size_t)IDIM * HDIM];
__device__ __nv_bfloat16 g_o1h[(size_t)NSEG * SEG * IDIM];
__device__ __nv_bfloat16 g_o1l[(size_t)NSEG * SEG * IDIM];

// ---------------------------------------------------------------------------
// Helpers
// ---------------------------------------------------------------------------
__device__ __forceinline__ uint32_t smaddr(const void* p) {
    return (uint32_t)__cvta_generic_to_shared(p);
}
__device__ __forceinline__ void ldsm4(uint32_t r[4], uint32_t a) {
    asm volatile("ldmatrix.sync.aligned.m8n8.x4.shared.b16 {%0,%1,%2,%3},[%4];"
        : "=r"(r[0]), "=r"(r[1]), "=r"(r[2]), "=r"(r[3]) : "r"(a));
}
__device__ __forceinline__ void ldsm4t(uint32_t r[4], uint32_t a) {
    asm volatile("ldmatrix.sync.aligned.m8n8.x4.trans.shared.b16 {%0,%1,%2,%3},[%4];"
        : "=r"(r[0]), "=r"(r[1]), "=r"(r[2]), "=r"(r[3]) : "r"(a));
}
__device__ __forceinline__ void mma_bf16(float c[4], const uint32_t a[4],
                                         const uint32_t b[2]) {
    asm volatile(
        "mma.sync.aligned.m16n8k16.row.col.f32.bf16.bf16.f32 "
        "{%0,%1,%2,%3},{%4,%5,%6,%7},{%8,%9},{%0,%1,%2,%3};"
        : "+f"(c[0]), "+f"(c[1]), "+f"(c[2]), "+f"(c[3])
        : "r"(a[0]), "r"(a[1]), "r"(a[2]), "r"(a[3]), "r"(b[0]), "r"(b[1]));
}
__device__ __forceinline__ void split2(float x, float y, uint32_t& hi, uint32_t& lo) {
    __nv_bfloat16 hx = __float2bfloat16(x), hy = __float2bfloat16(y);
    __nv_bfloat16 lx = __float2bfloat16(x - __bfloat162float(hx));
    __nv_bfloat16 ly = __float2bfloat16(y - __bfloat162float(hy));
    hi = (uint32_t)__bfloat16_as_ushort(hx) | ((uint32_t)__bfloat16_as_ushort(hy) << 16);
    lo = (uint32_t)__bfloat16_as_ushort(lx) | ((uint32_t)__bfloat16_as_ushort(ly) << 16);
}
__device__ __forceinline__ void cp16(void* dst, const void* src) {
    asm volatile("cp.async.cg.shared.global [%0],[%1],16;"
        :: "r"(smaddr(dst)), "l"(src));
}
__device__ __forceinline__ void cp_commit() {
    asm volatile("cp.async.commit_group;");
}
template <int N> __device__ __forceinline__ void cp_wait() {
    asm volatile("cp.async.wait_group %0;" :: "n"(N));
}

// ---------------------------------------------------------------------------
// Init
// ---------------------------------------------------------------------------
__global__ void init_kernel() {
    int tid = blockIdx.x * blockDim.x + threadIdx.x;
    int stride = gridDim.x * blockDim.x;
    for (int i = tid; i < NEXP * SEG; i += stride) {
        g_row_token[i] = 0;
        g_row_weight[i] = 0.0f;
    }
    if (tid < NEXP) { g_cnt[tid] = 0; g_disp[tid] = 0; g_psum[tid] = 0.0f; }
    if (tid == 0) g_zsum = 0.0f;
}

// ---------------------------------------------------------------------------
// fp32 -> bf16 hi/lo split conversion for all operands. blockIdx.y = tensor.
// ---------------------------------------------------------------------------
__global__ __launch_bounds__(256) void convert_kernel(
    const float* __restrict__ x, const float* __restrict__ gw,
    const float* __restrict__ uw, const float* __restrict__ dw,
    const float* __restrict__ sgw, const float* __restrict__ suw,
    const float* __restrict__ sdw)
{
    const float* src; __nv_bfloat16 *dh, *dl; size_t n;
    switch (blockIdx.y) {
        case 0: src = x;   dh = g_xh;   dl = g_xl;   n = (size_t)NTOK * HDIM; break;
        case 1: src = gw;  dh = g_gwh;  dl = g_gwl;  n = (size_t)NEXP * HDIM * IDIM; break;
        case 2: src = uw;  dh = g_uwh;  dl = g_uwl;  n = (size_t)NEXP * HDIM * IDIM; break;
        case 3: src = dw;  dh = g_dwh;  dl = g_dwl;  n = (size_t)NEXP * IDIM * HDIM; break;
        case 4: src = sgw; dh = g_sgwh; dl = g_sgwl; n = (size_t)HDIM * IDIM; break;
        case 5: src = suw; dh = g_suwh; dl = g_suwl; n = (size_t)HDIM * IDIM; break;
        default: src = sdw; dh = g_sdwh; dl = g_sdwl; n = (size_t)IDIM * HDIM; break;
    }
    size_t n4 = n >> 2;
    size_t stride = (size_t)gridDim.x * blockDim.x;
    for (size_t i = (size_t)blockIdx.x * blockDim.x + threadIdx.x; i < n4; i += stride) {
        float4 v = ((const float4*)src)[i];
        uint32_t h0, l0, h1, l1;
        split2(v.x, v.y, h0, l0);
        split2(v.z, v.w, h1, l1);
        ((uint2*)dh)[i] = make_uint2(h0, h1);
        ((uint2*)dl)[i] = make_uint2(l0, l1);
    }
}

// ---------------------------------------------------------------------------
// Router (unchanged — validated)
// ---------------------------------------------------------------------------
__global__ __launch_bounds__(256) void router_kernel(
    const float* __restrict__ x, const float* __restrict__ rw,
    float* __restrict__ out)
{
    __shared__ float s_rw[HDIM * NEXP];
    int tid = threadIdx.x;
    for (int i = tid; i < HDIM * NEXP; i += 256) s_rw[i] = rw[i];
    __syncthreads();

    int warp = tid >> 5, lane = tid & 31;
    int t = blockIdx.x * 8 + warp;

    float acc[NEXP];
#pragma unroll
    for (int e = 0; e < NEXP; e++) acc[e] = 0.0f;

    const float* xr = x + (size_t)t * HDIM;
    for (int h0 = 0; h0 < HDIM; h0 += 32) {
        float xv = xr[h0 + lane];
        const float4* r = (const float4*)&s_rw[(size_t)(h0 + lane) * NEXP];
        float4 r0 = r[0], r1 = r[1];
        acc[0] += xv * r0.x; acc[1] += xv * r0.y;
        acc[2] += xv * r0.z; acc[3] += xv * r0.w;
        acc[4] += xv * r1.x; acc[5] += xv * r1.y;
        acc[6] += xv * r1.z; acc[7] += xv * r1.w;
    }
#pragma unroll
    for (int e = 0; e < NEXP; e++)
#pragma unroll
        for (int off = 16; off; off >>= 1)
            acc[e] += __shfl_xor_sync(0xffffffffu, acc[e], off);

    if (lane == 0) {
        float mx = acc[0];
#pragma unroll
        for (int e = 1; e < NEXP; e++) mx = fmaxf(mx, acc[e]);
        float p[NEXP], s = 0.0f;
#pragma unroll
        for (int e = 0; e < NEXP; e++) { p[e] = expf(acc[e] - mx); s += p[e]; }
        float inv = 1.0f / s;
#pragma unroll
        for (int e = 0; e < NEXP; e++) p[e] *= inv;

        float lse = logf(s) + mx;
        atomicAdd(&g_zsum, lse * lse);
#pragma unroll
        for (int e = 0; e < NEXP; e++) atomicAdd(&g_psum[e], p[e]);
#pragma unroll
        for (int e = 0; e < NEXP; e++)
            out[OUT_LOGITS + (size_t)t * NEXP + e] = acc[e];

        int e1 = 0;
#pragma unroll
        for (int e = 1; e < NEXP; e++) if (p[e] > p[e1]) e1 = e;
        int e2 = (e1 == 0) ? 1 : 0;
#pragma unroll
        for (int e = 0; e < NEXP; e++) if (e != e1 && p[e] > p[e2]) e2 = e;

        float ws = p[e1] + p[e2];
        float w1 = p[e1] / ws, w2 = p[e2] / ws;
        atomicAdd(&g_disp[e1], 1);
        atomicAdd(&g_disp[e2], 1);
        int p1 = atomicAdd(&g_cnt[e1], 1);
        g_row_token[e1 * SEG + p1] = t;
        g_row_weight[e1 * SEG + p1] = w1;
        int p2 = atomicAdd(&g_cnt[e2], 1);
        g_row_token[e2 * SEG + p2] = t;
        g_row_weight[e2 * SEG + p2] = w2;
    }
}

__global__ void finalize_kernel(float* __restrict__ out) {
    if (threadIdx.x == 0 && blockIdx.x == 0) {
        float aux = 0.0f;
        for (int e = 0; e < NEXP; e++) {
            float tpe = (float)g_disp[e] / (2.0f * (float)NTOK);
            float ppe = g_psum[e] / (float)NTOK;
            aux += tpe * ppe;
        }
        out[OUT_AUX] = (float)NEXP * aux;
        out[OUT_Z] = g_zsum / (float)NTOK;
    }
}

// ---------------------------------------------------------------------------
// Shared-memory stage structs (dynamic smem, 5 stages)
// ---------------------------------------------------------------------------
struct alignas(16) G1Smem {
    __nv_bfloat16 Ah[STAGES][128][24];
    __nv_bfloat16 Al[STAGES][128][24];
    __nv_bfloat16 Bh[STAGES][16][136];   // cols 0-63 gate, 64-127 up
    __nv_bfloat16 Bl[STAGES][16][136];
    int tok[128];
};
struct alignas(16) G2Smem {
    __nv_bfloat16 Ah[STAGES][128][24];
    __nv_bfloat16 Al[STAGES][128][24];
    __nv_bfloat16 Bh[STAGES][16][136];
    __nv_bfloat16 Bl[STAGES][16][136];
    int   tok[128];
    float w[128];
};

// ---------------------------------------------------------------------------
// GEMM1: gathered rows -> silu(X@Gw) * (X@Uw), bf16x3, cp.async 5-stage.
// Block 128 x (64 gate + 64 up), 8 warps, warp tile 32x64.
// ---------------------------------------------------------------------------
__global__ __launch_bounds__(256, 2) void gemm1_kernel()
{
    const int seg = blockIdx.y >> 5;
    const int base_m = (blockIdx.y & 31) * 128;
    const __nv_bfloat16 *gwh, *gwl, *uwh, *uwl;
    if (seg < NEXP) {
        if (base_m >= g_cnt[seg]) return;
        size_t off = (size_t)seg * HDIM * IDIM;
        gwh = g_gwh + off; gwl = g_gwl + off;
        uwh = g_uwh + off; uwl = g_uwl + off;
    } else {
        gwh = g_sgwh; gwl = g_sgwl; uwh = g_suwh; uwl = g_suwl;
    }

    extern __shared__ char smem_raw[];
    G1Smem& S = *(G1Smem*)smem_raw;

    const int tid = threadIdx.x;
    const int lane = tid & 31, wid = tid >> 5;
    const int wm = wid & 3, wn = wid >> 2;
    const int nb = blockIdx.x;

    if (tid < 128)
        S.tok[tid] = (seg < NEXP) ? g_row_token[seg * SEG + base_m + tid]
                                  : (base_m + tid);
    __syncthreads();

    // per-thread cp.async source pointers
    const int am = tid >> 1, ac = (tid & 1) * 8;
    const size_t arow = (size_t)S.tok[am] * HDIM + ac;
    const __nv_bfloat16* aSrcH = g_xh + arow;
    const __nv_bfloat16* aSrcL = g_xl + arow;
    const int brow = tid >> 4, bcol = (tid & 15) * 8;
    const __nv_bfloat16 *bSrcH, *bSrcL;
    {
        size_t boff = (size_t)brow * IDIM + nb * 64;
        if (bcol < 64) { bSrcH = gwh + boff + bcol;      bSrcL = gwl + boff + bcol; }
        else           { bSrcH = uwh + boff + bcol - 64; bSrcL = uwl + boff + bcol - 64; }
    }

    float acc[2][8][4];
#pragma unroll
    for (int i = 0; i < 2; i++)
#pragma unroll
        for (int j = 0; j < 8; j++)
#pragma unroll
            for (int q = 0; q < 4; q++) acc[i][j][q] = 0.0f;

    const int KSTEPS = HDIM / 16;   // 64
#pragma unroll 1
    for (int s = 0; s < STAGES - 1; s++) {
        int k0 = s * 16;
        cp16(&S.Ah[s][am][ac], aSrcH + k0);
        cp16(&S.Al[s][am][ac], aSrcL + k0);
        cp16(&S.Bh[s][brow][bcol], bSrcH + (size_t)k0 * IDIM);
        cp16(&S.Bl[s][brow][bcol], bSrcL + (size_t)k0 * IDIM);
        cp_commit();
    }

    int s_use = 0, s_fill = STAGES - 1;
#pragma unroll 1
    for (int kt = 0; kt < KSTEPS; kt++) {
        cp_wait<STAGES - 2>();
        __syncthreads();

        int kn = kt + STAGES - 1;
        if (kn < KSTEPS) {
            int k0 = kn * 16;
            cp16(&S.Ah[s_fill][am][ac], aSrcH + k0);
            cp16(&S.Al[s_fill][am][ac], aSrcL + k0);
            cp16(&S.Bh[s_fill][brow][bcol], bSrcH + (size_t)k0 * IDIM);
            cp16(&S.Bl[s_fill][brow][bcol], bSrcL + (size_t)k0 * IDIM);
        }
        cp_commit();

        const int s = s_use;
        uint32_t ah[2][4], al[2][4];
#pragma unroll
        for (int mt = 0; mt < 2; mt++) {
            int r = wm * 32 + mt * 16 + (lane & 15);
            int c = (lane >> 4) * 8;
            ldsm4(ah[mt], smaddr(&S.Ah[s][r][c]));
            ldsm4(al[mt], smaddr(&S.Al[s][r][c]));
        }
#pragma unroll
        for (int g = 0; g < 4; g++) {
            int n0 = ((g & 2) ? 64 : 0) + wn * 32 + (g & 1) * 16;
            int bc = n0 + (lane >> 4) * 8;
            int brr = lane & 15;
            uint32_t bh[4], bl[4];
            ldsm4t(bh, smaddr(&S.Bh[s][brr][bc]));
            ldsm4t(bl, smaddr(&S.Bl[s][brr][bc]));
            int j = g * 2;
#pragma unroll
            for (int mt = 0; mt < 2; mt++) {
                mma_bf16(acc[mt][j],     ah[mt], bh);
                mma_bf16(acc[mt][j],     ah[mt], bl);
                mma_bf16(acc[mt][j],     al[mt], bh);
                mma_bf16(acc[mt][j + 1], ah[mt], bh + 2);
                mma_bf16(acc[mt][j + 1], ah[mt], bl + 2);
                mma_bf16(acc[mt][j + 1], al[mt], bh + 2);
            }
        }
        if (++s_use == STAGES) s_use = 0;
        if (++s_fill == STAGES) s_fill = 0;
    }

    // epilogue: silu(gate)*up -> g_o1h/g_o1l (acc j 0-3 gate, 4-7 up)
#pragma unroll
    for (int mt = 0; mt < 2; mt++) {
        int r0 = base_m + wm * 32 + mt * 16 + (lane >> 2);
        size_t row0 = (size_t)seg * SEG + r0;
        size_t row1 = row0 + 8;
#pragma unroll
        for (int jg = 0; jg < 4; jg++) {
            float* G = acc[mt][jg];
            float* U = acc[mt][4 + jg];
            int col = nb * 64 + wn * 32 + jg * 8 + (lane & 3) * 2;
            float o0 = U[0] * G[0] / (1.0f + __expf(-G[0]));
            float o1 = U[1] * G[1] / (1.0f + __expf(-G[1]));
            float o2 = U[2] * G[2] / (1.0f + __expf(-G[2]));
            float o3 = U[3] * G[3] / (1.0f + __expf(-G[3]));
            uint32_t h01, l01, h23, l23;
            split2(o0, o1, h01, l01);
            split2(o2, o3, h23, l23);
            *(uint32_t*)&g_o1h[row0 * IDIM + col] = h01;
            *(uint32_t*)&g_o1l[row0 * IDIM + col] = l01;
            *(uint32_t*)&g_o1h[row1 * IDIM + col] = h23;
            *(uint32_t*)&g_o1l[row1 * IDIM + col] = l23;
        }
    }
}

// ---------------------------------------------------------------------------
// GEMM2: g_o1 @ down_w, weight-scaled atomic scatter. Same pipeline.
// ---------------------------------------------------------------------------
__global__ __launch_bounds__(256, 2) void gemm2_kernel(float* __restrict__ out)
{
    const int seg = blockIdx.y >> 5;
    const int base_m = (blockIdx.y & 31) * 128;
    const __nv_bfloat16 *bwh, *bwl;
    if (seg < NEXP) {
        if (base_m >= g_cnt[seg]) return;
        size_t off = (size_t)seg * IDIM * HDIM;
        bwh = g_dwh + off; bwl = g_dwl + off;
    } else { bwh = g_sdwh; bwl = g_sdwl; }

    extern __shared__ char smem_raw[];
    G2Smem& S = *(G2Smem*)smem_raw;

    const int tid = threadIdx.x;
    const int lane = tid & 31, wid = tid >> 5;
    const int wm = wid & 3, wn = wid >> 2;
    const int nb = blockIdx.x;

    if (tid < 128) {
        if (seg < NEXP) {
            S.tok[tid] = g_row_token[seg * SEG + base_m + tid];
            S.w[tid]   = g_row_weight[seg * SEG + base_m + tid];
        } else { S.tok[tid] = base_m + tid; S.w[tid] = 1.0f; }
    }
    __syncthreads();

    const int am = tid >> 1, ac = (tid & 1) * 8;
    const size_t arow = ((size_t)seg * SEG + base_m + am) * IDIM + ac;
    const __nv_bfloat16* aSrcH = g_o1h + arow;
    const __nv_bfloat16* aSrcL = g_o1l + arow;
    const int brow = tid >> 4, bcol = (tid & 15) * 8;
    const size_t boff = (size_t)brow * HDIM + nb * 128 + bcol;
    const __nv_bfloat16* bSrcH = bwh + boff;
    const __nv_bfloat16* bSrcL = bwl + boff;

    float acc[2][8][4];
#pragma unroll
    for (int i = 0; i < 2; i++)
#pragma unroll
        for (int j = 0; j < 8; j++)
#pragma unroll
            for (int q = 0; q < 4; q++) acc[i][j][q] = 0.0f;

    const int KSTEPS = IDIM / 16;   // 128
#pragma unroll 1
    for (int s = 0; s < STAGES - 1; s++) {
        int k0 = s * 16;
        cp16(&S.Ah[s][am][ac], aSrcH + k0);
        cp16(&S.Al[s][am][ac], aSrcL + k0);
        cp16(&S.Bh[s][brow][bcol], bSrcH + (size_t)k0 * HDIM);
        cp16(&S.Bl[s][brow][bcol], bSrcL + (size_t)k0 * HDIM);
        cp_commit();
    }

    int s_use = 0, s_fill = STAGES - 1;
#pragma unroll 1
    for (int kt = 0; kt < KSTEPS; kt++) {
        cp_wait<STAGES - 2>();
        __syncthreads();

        int kn = kt + STAGES - 1;
        if (kn < KSTEPS) {
            int k0 = kn * 16;
            cp16(&S.Ah[s_fill][am][ac], aSrcH + k0);
            cp16(&S.Al[s_fill][am][ac], aSrcL + k0);
            cp16(&S.Bh[s_fill][brow][bcol], bSrcH + (size_t)k0 * HDIM);
            cp16(&S.Bl[s_fill][brow][bcol], bSrcL + (size_t)k0 * HDIM);
        }
        cp_commit();

        const int s = s_use;
        uint32_t ah[2][4], al[2][4];
#pragma unroll
        for (int mt = 0; mt < 2; mt++) {
            int r = wm * 32 + mt * 16 + (lane & 15);
            int c = (lane >> 4) * 8;
            ldsm4(ah[mt], smaddr(&S.Ah[s][r][c]));
            ldsm4(al[mt], smaddr(&S.Al[s][r][c]));
        }
#pragma unroll
        for (int g = 0; g < 4; g++) {
            int n0 = wn * 64 + g * 16;
            int bc = n0 + (lane >> 4) * 8;
            int brr = lane & 15;
            uint32_t bh[4], bl[4];
            ldsm4t(bh, smaddr(&S.Bh[s][brr][bc]));
            ldsm4t(bl, smaddr(&S.Bl[s][brr][bc]));
            int j = g * 2;
#pragma unroll
            for (int mt = 0; mt < 2; mt++) {
                mma_bf16(acc[mt][j],     ah[mt], bh);
                mma_bf16(acc[mt][j],     ah[mt], bl);
                mma_bf16(acc[mt][j],     al[mt], bh);
                mma_bf16(acc[mt][j + 1], ah[mt], bh + 2);
                mma_bf16(acc[mt][j + 1], ah[mt], bl + 2);
                mma_bf16(acc[mt][j + 1], al[mt], bh + 2);
            }
        }
        if (++s_use == STAGES) s_use = 0;
        if (++s_fill == STAGES) s_fill = 0;
    }

    // epilogue: weight-scaled scatter-add
#pragma unroll
    for (int mt = 0; mt < 2; mt++) {
        int rl0 = wm * 32 + mt * 16 + (lane >> 2);
        int t0 = S.tok[rl0], t1 = S.tok[rl0 + 8];
        float w0 = S.w[rl0], w1 = S.w[rl0 + 8];
#pragma unroll
        for (int j = 0; j < 8; j++) {
            float* C = acc[mt][j];
            int col = nb * 128 + wn * 64 + j * 8 + (lane & 3) * 2;
            atomicAdd(&out[(size_t)t0 * HDIM + col],     w0 * C[0]);
            atomicAdd(&out[(size_t)t0 * HDIM + col + 1], w0 * C[1]);
            atomicAdd(&out[(size_t)t1 * HDIM + col],     w1 * C[2]);
            atomicAdd(&out[(size_t)t1 * HDIM + col + 1], w1 * C[3]);
        }
    }
}

// ---------------------------------------------------------------------------
// Launch (finalize moved after GEMMs so ncu -s 5 captures a GEMM)
// ---------------------------------------------------------------------------
extern "C" void kernel_launch(void* const* d_in, const int* in_sizes, int n_in,
                              void* d_out, int out_size) {
    (void)in_sizes; (void)n_in; (void)out_size;
    const float* x   = (const float*)d_in[0];
    const float* rw  = (const float*)d_in[1];
    const float* gw  = (const float*)d_in[2];
    const float* uw  = (const float*)d_in[3];
    const float* dw  = (const float*)d_in[4];
    const float* sgw = (const float*)d_in[5];
    const float* suw = (const float*)d_in[6];
    const float* sdw = (const float*)d_in[7];
    float* out = (float*)d_out;

    cudaFuncSetAttribute(gemm1_kernel,
        cudaFuncAttributeMaxDynamicSharedMemorySize, (int)sizeof(G1Smem));
    cudaFuncSetAttribute(gemm2_kernel,
        cudaFuncAttributeMaxDynamicSharedMemorySize, (int)sizeof(G2Smem));

    cudaMemsetAsync(d_out, 0, (size_t)NTOK * HDIM * sizeof(float));
    init_kernel<<<64, 256>>>();
    convert_kernel<<<dim3(2048, 7), 256>>>(x, gw, uw, dw, sgw, suw, sdw);
    router_kernel<<<NTOK / 8, 256>>>(x, rw, out);

    dim3 g1(IDIM / 64, NSEG * 32);      // (32, 288)
    gemm1_kernel<<<g1, 256, sizeof(G1Smem)>>>();

    dim3 g2(HDIM / 128, NSEG * 32);     // (8, 288)
    gemm2_kernel<<<g2, 256, sizeof(G2Smem)>>>(out);

    finalize_kernel<<<1, 32>>>(out);
}

// round 11
// speedup vs baseline: 2.5653x; 2.3510x over previous
#include <cuda_runtime.h>
#include <cuda_fp16.h>
#include <cstdint>
#include <cstddef>

// ---------------------------------------------------------------------------
// Problem constants
// ---------------------------------------------------------------------------
#define HDIM 1024
#define IDIM 2048
#define NEXP 8
#define NTOK 4096
#define SEG  4096
#define NSEG 9               // 8 routed experts + 1 shared "expert"
#define STAGES 8

#define OUT_AUX    ((size_t)NTOK * HDIM)
#define OUT_Z      (OUT_AUX + 1)
#define OUT_LOGITS (OUT_AUX + 2)

// ---------------------------------------------------------------------------
// Static device scratch
// ---------------------------------------------------------------------------
__device__ int   g_row_token[NEXP * SEG];
__device__ float g_row_weight[NEXP * SEG];
__device__ int   g_cnt[NEXP];
__device__ int   g_disp[NEXP];
__device__ float g_psum[NEXP];
__device__ float g_zsum;

// fp16 copies of all GEMM operands (converted once per launch)
__device__ __half g_x16[(size_t)NTOK * HDIM];
__device__ __half g_gw16[(size_t)NEXP * HDIM * IDIM];
__device__ __half g_uw16[(size_t)NEXP * HDIM * IDIM];
__device__ __half g_dw16[(size_t)NEXP * IDIM * HDIM];
__device__ __half g_sgw16[(size_t)HDIM * IDIM];
__device__ __half g_suw16[(size_t)HDIM * IDIM];
__device__ __half g_sdw16[(size_t)IDIM * HDIM];
__device__ __half g_o116[(size_t)NSEG * SEG * IDIM];

// ---------------------------------------------------------------------------
// Helpers
// ---------------------------------------------------------------------------
__device__ __forceinline__ uint32_t smaddr(const void* p) {
    return (uint32_t)__cvta_generic_to_shared(p);
}
__device__ __forceinline__ void ldsm4(uint32_t r[4], uint32_t a) {
    asm volatile("ldmatrix.sync.aligned.m8n8.x4.shared.b16 {%0,%1,%2,%3},[%4];"
        : "=r"(r[0]), "=r"(r[1]), "=r"(r[2]), "=r"(r[3]) : "r"(a));
}
__device__ __forceinline__ void ldsm4t(uint32_t r[4], uint32_t a) {
    asm volatile("ldmatrix.sync.aligned.m8n8.x4.trans.shared.b16 {%0,%1,%2,%3},[%4];"
        : "=r"(r[0]), "=r"(r[1]), "=r"(r[2]), "=r"(r[3]) : "r"(a));
}
__device__ __forceinline__ void mma_f16(float c[4], const uint32_t a[4],
                                        const uint32_t b[2]) {
    asm volatile(
        "mma.sync.aligned.m16n8k16.row.col.f32.f16.f16.f32 "
        "{%0,%1,%2,%3},{%4,%5,%6,%7},{%8,%9},{%0,%1,%2,%3};"
        : "+f"(c[0]), "+f"(c[1]), "+f"(c[2]), "+f"(c[3])
        : "r"(a[0]), "r"(a[1]), "r"(a[2]), "r"(a[3]), "r"(b[0]), "r"(b[1]));
}
__device__ __forceinline__ uint32_t pack2h(float x, float y) {
    __half2 h = __floats2half2_rn(x, y);
    return *(uint32_t*)&h;
}
__device__ __forceinline__ void cp16(void* dst, const void* src) {
    asm volatile("cp.async.cg.shared.global [%0],[%1],16;"
        :: "r"(smaddr(dst)), "l"(src));
}
__device__ __forceinline__ void cp_commit() {
    asm volatile("cp.async.commit_group;");
}
template <int N> __device__ __forceinline__ void cp_wait() {
    asm volatile("cp.async.wait_group %0;" :: "n"(N));
}

// ---------------------------------------------------------------------------
// Init
// ---------------------------------------------------------------------------
__global__ void init_kernel() {
    int tid = blockIdx.x * blockDim.x + threadIdx.x;
    int stride = gridDim.x * blockDim.x;
    for (int i = tid; i < NEXP * SEG; i += stride) {
        g_row_token[i] = 0;
        g_row_weight[i] = 0.0f;
    }
    if (tid < NEXP) { g_cnt[tid] = 0; g_disp[tid] = 0; g_psum[tid] = 0.0f; }
    if (tid == 0) g_zsum = 0.0f;
}

// ---------------------------------------------------------------------------
// fp32 -> fp16 conversion for all operands. blockIdx.y = tensor.
// ---------------------------------------------------------------------------
__global__ __launch_bounds__(256) void convert_kernel(
    const float* __restrict__ x, const float* __restrict__ gw,
    const float* __restrict__ uw, const float* __restrict__ dw,
    const float* __restrict__ sgw, const float* __restrict__ suw,
    const float* __restrict__ sdw)
{
    const float* src; __half* dh; size_t n;
    switch (blockIdx.y) {
        case 0: src = x;   dh = g_x16;   n = (size_t)NTOK * HDIM; break;
        case 1: src = gw;  dh = g_gw16;  n = (size_t)NEXP * HDIM * IDIM; break;
        case 2: src = uw;  dh = g_uw16;  n = (size_t)NEXP * HDIM * IDIM; break;
        case 3: src = dw;  dh = g_dw16;  n = (size_t)NEXP * IDIM * HDIM; break;
        case 4: src = sgw; dh = g_sgw16; n = (size_t)HDIM * IDIM; break;
        case 5: src = suw; dh = g_suw16; n = (size_t)HDIM * IDIM; break;
        default: src = sdw; dh = g_sdw16; n = (size_t)IDIM * HDIM; break;
    }
    size_t n4 = n >> 2;
    size_t stride = (size_t)gridDim.x * blockDim.x;
    for (size_t i = (size_t)blockIdx.x * blockDim.x + threadIdx.x; i < n4; i += stride) {
        float4 v = ((const float4*)src)[i];
        ((uint2*)dh)[i] = make_uint2(pack2h(v.x, v.y), pack2h(v.z, v.w));
    }
}

// ---------------------------------------------------------------------------
// Router (unchanged — validated)
// ---------------------------------------------------------------------------
__global__ __launch_bounds__(256) void router_kernel(
    const float* __restrict__ x, const float* __restrict__ rw,
    float* __restrict__ out)
{
    __shared__ float s_rw[HDIM * NEXP];
    int tid = threadIdx.x;
    for (int i = tid; i < HDIM * NEXP; i += 256) s_rw[i] = rw[i];
    __syncthreads();

    int warp = tid >> 5, lane = tid & 31;
    int t = blockIdx.x * 8 + warp;

    float acc[NEXP];
#pragma unroll
    for (int e = 0; e < NEXP; e++) acc[e] = 0.0f;

    const float* xr = x + (size_t)t * HDIM;
    for (int h0 = 0; h0 < HDIM; h0 += 32) {
        float xv = xr[h0 + lane];
        const float4* r = (const float4*)&s_rw[(size_t)(h0 + lane) * NEXP];
        float4 r0 = r[0], r1 = r[1];
        acc[0] += xv * r0.x; acc[1] += xv * r0.y;
        acc[2] += xv * r0.z; acc[3] += xv * r0.w;
        acc[4] += xv * r1.x; acc[5] += xv * r1.y;
        acc[6] += xv * r1.z; acc[7] += xv * r1.w;
    }
#pragma unroll
    for (int e = 0; e < NEXP; e++)
#pragma unroll
        for (int off = 16; off; off >>= 1)
            acc[e] += __shfl_xor_sync(0xffffffffu, acc[e], off);

    if (lane == 0) {
        float mx = acc[0];
#pragma unroll
        for (int e = 1; e < NEXP; e++) mx = fmaxf(mx, acc[e]);
        float p[NEXP], s = 0.0f;
#pragma unroll
        for (int e = 0; e < NEXP; e++) { p[e] = expf(acc[e] - mx); s += p[e]; }
        float inv = 1.0f / s;
#pragma unroll
        for (int e = 0; e < NEXP; e++) p[e] *= inv;

        float lse = logf(s) + mx;
        atomicAdd(&g_zsum, lse * lse);
#pragma unroll
        for (int e = 0; e < NEXP; e++) atomicAdd(&g_psum[e], p[e]);
#pragma unroll
        for (int e = 0; e < NEXP; e++)
            out[OUT_LOGITS + (size_t)t * NEXP + e] = acc[e];

        int e1 = 0;
#pragma unroll
        for (int e = 1; e < NEXP; e++) if (p[e] > p[e1]) e1 = e;
        int e2 = (e1 == 0) ? 1 : 0;
#pragma unroll
        for (int e = 0; e < NEXP; e++) if (e != e1 && p[e] > p[e2]) e2 = e;

        float ws = p[e1] + p[e2];
        float w1 = p[e1] / ws, w2 = p[e2] / ws;
        atomicAdd(&g_disp[e1], 1);
        atomicAdd(&g_disp[e2], 1);
        int p1 = atomicAdd(&g_cnt[e1], 1);
        g_row_token[e1 * SEG + p1] = t;
        g_row_weight[e1 * SEG + p1] = w1;
        int p2 = atomicAdd(&g_cnt[e2], 1);
        g_row_token[e2 * SEG + p2] = t;
        g_row_weight[e2 * SEG + p2] = w2;
    }
}

__global__ void finalize_kernel(float* __restrict__ out) {
    if (threadIdx.x == 0 && blockIdx.x == 0) {
        float aux = 0.0f;
        for (int e = 0; e < NEXP; e++) {
            float tpe = (float)g_disp[e] / (2.0f * (float)NTOK);
            float ppe = g_psum[e] / (float)NTOK;
            aux += tpe * ppe;
        }
        out[OUT_AUX] = (float)NEXP * aux;
        out[OUT_Z] = g_zsum / (float)NTOK;
    }
}

// ---------------------------------------------------------------------------
// Shared-memory stage structs (dynamic smem, 8 stages, fp16 single)
// ---------------------------------------------------------------------------
struct alignas(16) G1Smem {
    __half A[STAGES][128][24];
    __half B[STAGES][16][136];   // cols 0-63 gate, 64-127 up
    int tok[128];
};
struct alignas(16) G2Smem {
    __half A[STAGES][128][24];
    __half B[STAGES][16][136];
    int   tok[128];
    float w[128];
};

// ---------------------------------------------------------------------------
// GEMM1: gathered rows -> silu(X@Gw) * (X@Uw), fp16 single-pass,
// cp.async 8-stage. Block 128 x (64 gate + 64 up), 8 warps, warp tile 32x64.
// ---------------------------------------------------------------------------
__global__ __launch_bounds__(256, 2) void gemm1_kernel()
{
    const int seg = blockIdx.y >> 5;
    const int base_m = (blockIdx.y & 31) * 128;
    const __half *gw, *uw;
    if (seg < NEXP) {
        if (base_m >= g_cnt[seg]) return;
        size_t off = (size_t)seg * HDIM * IDIM;
        gw = g_gw16 + off; uw = g_uw16 + off;
    } else {
        gw = g_sgw16; uw = g_suw16;
    }

    extern __shared__ char smem_raw[];
    G1Smem& S = *(G1Smem*)smem_raw;

    const int tid = threadIdx.x;
    const int lane = tid & 31, wid = tid >> 5;
    const int wm = wid & 3, wn = wid >> 2;
    const int nb = blockIdx.x;

    if (tid < 128)
        S.tok[tid] = (seg < NEXP) ? g_row_token[seg * SEG + base_m + tid]
                                  : (base_m + tid);
    __syncthreads();

    // per-thread cp.async sources: 1 A chunk + 1 B chunk per stage
    const int am = tid >> 1, ac = (tid & 1) * 8;
    const __half* aSrc = g_x16 + (size_t)S.tok[am] * HDIM + ac;
    const int brow = tid >> 4, bcol = (tid & 15) * 8;
    const __half* bSrc;
    {
        size_t boff = (size_t)brow * IDIM + nb * 64;
        bSrc = (bcol < 64) ? (gw + boff + bcol) : (uw + boff + bcol - 64);
    }

    float acc[2][8][4];
#pragma unroll
    for (int i = 0; i < 2; i++)
#pragma unroll
        for (int j = 0; j < 8; j++)
#pragma unroll
            for (int q = 0; q < 4; q++) acc[i][j][q] = 0.0f;

    const int KSTEPS = HDIM / 16;   // 64
#pragma unroll 1
    for (int s = 0; s < STAGES - 1; s++) {
        int k0 = s * 16;
        cp16(&S.A[s][am][ac], aSrc + k0);
        cp16(&S.B[s][brow][bcol], bSrc + (size_t)k0 * IDIM);
        cp_commit();
    }

    int s_use = 0, s_fill = STAGES - 1;
#pragma unroll 1
    for (int kt = 0; kt < KSTEPS; kt++) {
        cp_wait<STAGES - 2>();
        __syncthreads();

        int kn = kt + STAGES - 1;
        if (kn < KSTEPS) {
            int k0 = kn * 16;
            cp16(&S.A[s_fill][am][ac], aSrc + k0);
            cp16(&S.B[s_fill][brow][bcol], bSrc + (size_t)k0 * IDIM);
        }
        cp_commit();

        const int s = s_use;
        uint32_t ah[2][4];
#pragma unroll
        for (int mt = 0; mt < 2; mt++) {
            int r = wm * 32 + mt * 16 + (lane & 15);
            int c = (lane >> 4) * 8;
            ldsm4(ah[mt], smaddr(&S.A[s][r][c]));
        }
#pragma unroll
        for (int g = 0; g < 4; g++) {
            int n0 = ((g & 2) ? 64 : 0) + wn * 32 + (g & 1) * 16;
            int bc = n0 + (lane >> 4) * 8;
            int brr = lane & 15;
            uint32_t bh[4];
            ldsm4t(bh, smaddr(&S.B[s][brr][bc]));
            int j = g * 2;
#pragma unroll
            for (int mt = 0; mt < 2; mt++) {
                mma_f16(acc[mt][j],     ah[mt], bh);
                mma_f16(acc[mt][j + 1], ah[mt], bh + 2);
            }
        }
        if (++s_use == STAGES) s_use = 0;
        if (++s_fill == STAGES) s_fill = 0;
    }

    // epilogue: silu(gate)*up -> g_o116 (acc j 0-3 gate, 4-7 up)
#pragma unroll
    for (int mt = 0; mt < 2; mt++) {
        int r0 = base_m + wm * 32 + mt * 16 + (lane >> 2);
        size_t row0 = (size_t)seg * SEG + r0;
        size_t row1 = row0 + 8;
#pragma unroll
        for (int jg = 0; jg < 4; jg++) {
            float* G = acc[mt][jg];
            float* U = acc[mt][4 + jg];
            int col = nb * 64 + wn * 32 + jg * 8 + (lane & 3) * 2;
            float o0 = U[0] * G[0] / (1.0f + __expf(-G[0]));
            float o1 = U[1] * G[1] / (1.0f + __expf(-G[1]));
            float o2 = U[2] * G[2] / (1.0f + __expf(-G[2]));
            float o3 = U[3] * G[3] / (1.0f + __expf(-G[3]));
            *(uint32_t*)&g_o116[row0 * IDIM + col] = pack2h(o0, o1);
            *(uint32_t*)&g_o116[row1 * IDIM + col] = pack2h(o2, o3);
        }
    }
}

// ---------------------------------------------------------------------------
// GEMM2: g_o1 @ down_w, weight-scaled atomic scatter. Same pipeline.
// ---------------------------------------------------------------------------
__global__ __launch_bounds__(256, 2) void gemm2_kernel(float* __restrict__ out)
{
    const int seg = blockIdx.y >> 5;
    const int base_m = (blockIdx.y & 31) * 128;
    const __half* bw;
    if (seg < NEXP) {
        if (base_m >= g_cnt[seg]) return;
        bw = g_dw16 + (size_t)seg * IDIM * HDIM;
    } else bw = g_sdw16;

    extern __shared__ char smem_raw[];
    G2Smem& S = *(G2Smem*)smem_raw;

    const int tid = threadIdx.x;
    const int lane = tid & 31, wid = tid >> 5;
    const int wm = wid & 3, wn = wid >> 2;
    const int nb = blockIdx.x;

    if (tid < 128) {
        if (seg < NEXP) {
            S.tok[tid] = g_row_token[seg * SEG + base_m + tid];
            S.w[tid]   = g_row_weight[seg * SEG + base_m + tid];
        } else { S.tok[tid] = base_m + tid; S.w[tid] = 1.0f; }
    }
    __syncthreads();

    const int am = tid >> 1, ac = (tid & 1) * 8;
    const __half* aSrc = g_o116 + ((size_t)seg * SEG + base_m + am) * IDIM + ac;
    const int brow = tid >> 4, bcol = (tid & 15) * 8;
    const __half* bSrc = bw + (size_t)brow * HDIM + nb * 128 + bcol;

    float acc[2][8][4];
#pragma unroll
    for (int i = 0; i < 2; i++)
#pragma unroll
        for (int j = 0; j < 8; j++)
#pragma unroll
            for (int q = 0; q < 4; q++) acc[i][j][q] = 0.0f;

    const int KSTEPS = IDIM / 16;   // 128
#pragma unroll 1
    for (int s = 0; s < STAGES - 1; s++) {
        int k0 = s * 16;
        cp16(&S.A[s][am][ac], aSrc + k0);
        cp16(&S.B[s][brow][bcol], bSrc + (size_t)k0 * HDIM);
        cp_commit();
    }

    int s_use = 0, s_fill = STAGES - 1;
#pragma unroll 1
    for (int kt = 0; kt < KSTEPS; kt++) {
        cp_wait<STAGES - 2>();
        __syncthreads();

        int kn = kt + STAGES - 1;
        if (kn < KSTEPS) {
            int k0 = kn * 16;
            cp16(&S.A[s_fill][am][ac], aSrc + k0);
            cp16(&S.B[s_fill][brow][bcol], bSrc + (size_t)k0 * HDIM);
        }
        cp_commit();

        const int s = s_use;
        uint32_t ah[2][4];
#pragma unroll
        for (int mt = 0; mt < 2; mt++) {
            int r = wm * 32 + mt * 16 + (lane & 15);
            int c = (lane >> 4) * 8;
            ldsm4(ah[mt], smaddr(&S.A[s][r][c]));
        }
#pragma unroll
        for (int g = 0; g < 4; g++) {
            int n0 = wn * 64 + g * 16;
            int bc = n0 + (lane >> 4) * 8;
            int brr = lane & 15;
            uint32_t bh[4];
            ldsm4t(bh, smaddr(&S.B[s][brr][bc]));
            int j = g * 2;
#pragma unroll
            for (int mt = 0; mt < 2; mt++) {
                mma_f16(acc[mt][j],     ah[mt], bh);
                mma_f16(acc[mt][j + 1], ah[mt], bh + 2);
            }
        }
        if (++s_use == STAGES) s_use = 0;
        if (++s_fill == STAGES) s_fill = 0;
    }

    // epilogue: weight-scaled scatter-add
#pragma unroll
    for (int mt = 0; mt < 2; mt++) {
        int rl0 = wm * 32 + mt * 16 + (lane >> 2);
        int t0 = S.tok[rl0], t1 = S.tok[rl0 + 8];
        float w0 = S.w[rl0], w1 = S.w[rl0 + 8];
#pragma unroll
        for (int j = 0; j < 8; j++) {
            float* C = acc[mt][j];
            int col = nb * 128 + wn * 64 + j * 8 + (lane & 3) * 2;
            atomicAdd(&out[(size_t)t0 * HDIM + col],     w0 * C[0]);
            atomicAdd(&out[(size_t)t0 * HDIM + col + 1], w0 * C[1]);
            atomicAdd(&out[(size_t)t1 * HDIM + col],     w1 * C[2]);
            atomicAdd(&out[(size_t)t1 * HDIM + col + 1], w1 * C[3]);
        }
    }
}

// ---------------------------------------------------------------------------
// Launch
// ---------------------------------------------------------------------------
extern "C" void kernel_launch(void* const* d_in, const int* in_sizes, int n_in,
                              void* d_out, int out_size) {
    (void)in_sizes; (void)n_in; (void)out_size;
    const float* x   = (const float*)d_in[0];
    const float* rw  = (const float*)d_in[1];
    const float* gw  = (const float*)d_in[2];
    const float* uw  = (const float*)d_in[3];
    const float* dw  = (const float*)d_in[4];
    const float* sgw = (const float*)d_in[5];
    const float* suw = (const float*)d_in[6];
    const float* sdw = (const float*)d_in[7];
    float* out = (float*)d_out;

    cudaFuncSetAttribute(gemm1_kernel,
        cudaFuncAttributeMaxDynamicSharedMemorySize, (int)sizeof(G1Smem));
    cudaFuncSetAttribute(gemm2_kernel,
        cudaFuncAttributeMaxDynamicSharedMemorySize, (int)sizeof(G2Smem));

    cudaMemsetAsync(d_out, 0, (size_t)NTOK * HDIM * sizeof(float));
    init_kernel<<<64, 256>>>();
    convert_kernel<<<dim3(2048, 7), 256>>>(x, gw, uw, dw, sgw, suw, sdw);
    router_kernel<<<NTOK / 8, 256>>>(x, rw, out);

    dim3 g1(IDIM / 64, NSEG * 32);      // (32, 288)
    gemm1_kernel<<<g1, 256, sizeof(G1Smem)>>>();

    dim3 g2(HDIM / 128, NSEG * 32);     // (8, 288)
    gemm2_kernel<<<g2, 256, sizeof(G2Smem)>>>(out);

    finalize_kernel<<<1, 32>>>(out);
}